// round 1
// baseline (speedup 1.0000x reference)
#include <cuda_runtime.h>

#define LSEQ 2048
#define BATCH 8
// 1/sqrt(512)
#define ATT_SCALE 0.044194173824159216f

// Scratch for q/k/v projections: [B, C, L] each = 33.5 MB
__device__ float g_q[BATCH * 512 * LSEQ];
__device__ float g_k[BATCH * 512 * LSEQ];
__device__ float g_v[BATCH * 512 * LSEQ];

// ---------------------------------------------------------------------------
// Conv1d projection as tiled GEMM:
//   y[b, co, l] = bias[co] + sum_{ci,k} w[co, ci, k] * x[b, ci, l + k - 1]
// Block: 64 co x 64 l tile, 256 threads, 4x4 micro-tile per thread.
// ---------------------------------------------------------------------------
__global__ void __launch_bounds__(256) conv_qkv_kernel(
    const float* __restrict__ x, const float* __restrict__ w,
    const float* __restrict__ bias, int which)
{
    float* y = (which == 0) ? g_q : (which == 1) ? g_k : g_v;

    const int b   = blockIdx.z;
    const int co0 = blockIdx.y * 64;
    const int l0  = blockIdx.x * 64;
    const int tid = threadIdx.x;
    const int ty  = tid >> 4;   // co micro-row group (0..15)
    const int tx  = tid & 15;   // l  micro-col group (0..15)

    __shared__ float ws[16 * 3 * 64];   // [ci][k][co]
    __shared__ float xs[16][68];        // [ci][p], p = l - l0 + 1, valid 0..65

    float acc[4][4];
#pragma unroll
    for (int ii = 0; ii < 4; ii++)
#pragma unroll
        for (int jj = 0; jj < 4; jj++) acc[ii][jj] = 0.f;

    for (int ci0 = 0; ci0 < 512; ci0 += 16) {
        __syncthreads();
        // load weight chunk: 64co x 16ci x 3k = 3072 floats
#pragma unroll
        for (int r = 0; r < 12; r++) {
            int flat = tid + r * 256;
            int co   = flat / 48;
            int rem  = flat - co * 48;
            int ci   = rem / 3;
            int k    = rem - ci * 3;
            ws[(ci * 3 + k) * 64 + co] =
                w[(size_t)(co0 + co) * 1536 + (size_t)(ci0 + ci) * 3 + k];
        }
        // load x chunk: 16ci x 66 (with halo, zero-padded at sequence edges)
#pragma unroll
        for (int r = 0; r < 5; r++) {
            int flat = tid + r * 256;
            if (flat < 16 * 66) {
                int ci = flat / 66;
                int p  = flat - ci * 66;
                int gl = l0 - 1 + p;
                float v = 0.f;
                if (gl >= 0 && gl < LSEQ)
                    v = x[((size_t)b * 512 + ci0 + ci) * LSEQ + gl];
                xs[ci][p] = v;
            }
        }
        __syncthreads();

#pragma unroll 4
        for (int ci = 0; ci < 16; ci++) {
            float xv[6];
#pragma unroll
            for (int t = 0; t < 6; t++) xv[t] = xs[ci][tx * 4 + t];
#pragma unroll
            for (int k = 0; k < 3; k++) {
                float4 wv = *(const float4*)&ws[(ci * 3 + k) * 64 + ty * 4];
                float wa[4] = {wv.x, wv.y, wv.z, wv.w};
#pragma unroll
                for (int ii = 0; ii < 4; ii++)
#pragma unroll
                    for (int jj = 0; jj < 4; jj++)
                        acc[ii][jj] = fmaf(wa[ii], xv[jj + k], acc[ii][jj]);
            }
        }
    }

#pragma unroll
    for (int ii = 0; ii < 4; ii++) {
        int co   = co0 + ty * 4 + ii;
        float bv = bias[co];
        float4 o4;
        o4.x = acc[ii][0] + bv;
        o4.y = acc[ii][1] + bv;
        o4.z = acc[ii][2] + bv;
        o4.w = acc[ii][3] + bv;
        *(float4*)&y[((size_t)b * 512 + co) * LSEQ + l0 + tx * 4] = o4;
    }
}

// ---------------------------------------------------------------------------
// Flash attention, fp32. One block = one (b*h) head, 64 query positions.
// Threads: 256, (ty,tx) = 16x16 grid; S micro-tile 4x4; O micro-tile 4x4.
// smem (dynamic, 67584 B):
//   qs [64 d][64 i]   ks [64 d][64 j]   vts [64 j][68 d]   ps [64 i][68 j]
// ---------------------------------------------------------------------------
__global__ void __launch_bounds__(256) attn_kernel(float* __restrict__ out)
{
    extern __shared__ float sm[];
    float* qs  = sm;                 // 4096
    float* ks  = qs + 4096;          // 4096
    float* vts = ks + 4096;          // 64*68 = 4352
    float* ps  = vts + 64 * 68;      // 64*68 = 4352

    const int bh = blockIdx.y;            // 0..63 (b*H + h)
    const int i0 = blockIdx.x * 64;       // query tile origin
    const int tid = threadIdx.x;
    const int ty  = tid >> 4;
    const int tx  = tid & 15;
    const size_t base = (size_t)bh * 64 * LSEQ;   // head base: [bh*64 + d][l]

    // load Q tile: qs[d][i]
#pragma unroll
    for (int r = 0; r < 16; r++) {
        int flat = tid + r * 256;
        int d = flat >> 6, i = flat & 63;
        qs[d * 64 + i] = g_q[base + (size_t)d * LSEQ + i0 + i];
    }

    float m_run[4], l_run[4], o[4][4];
#pragma unroll
    for (int ii = 0; ii < 4; ii++) {
        m_run[ii] = -1e30f;
        l_run[ii] = 0.f;
#pragma unroll
        for (int dd = 0; dd < 4; dd++) o[ii][dd] = 0.f;
    }

    for (int m0 = 0; m0 < LSEQ; m0 += 64) {
        __syncthreads();   // previous PV done before overwriting ks/vts
        // load K tile [d][j] and V transposed [j][d]
#pragma unroll
        for (int r = 0; r < 16; r++) {
            int flat = tid + r * 256;
            int d = flat >> 6, j = flat & 63;
            float kv = g_k[base + (size_t)d * LSEQ + m0 + j];
            float vv = g_v[base + (size_t)d * LSEQ + m0 + j];
            ks[d * 64 + j]  = kv;
            vts[j * 68 + d] = vv;
        }
        __syncthreads();

        // S = Q^T K  (4x4 micro-tile)
        float s[4][4];
#pragma unroll
        for (int ii = 0; ii < 4; ii++)
#pragma unroll
            for (int jj = 0; jj < 4; jj++) s[ii][jj] = 0.f;

#pragma unroll 8
        for (int d = 0; d < 64; d++) {
            float4 qa = *(const float4*)&qs[d * 64 + ty * 4];
            float4 kb = *(const float4*)&ks[d * 64 + tx * 4];
            float qv[4] = {qa.x, qa.y, qa.z, qa.w};
            float kv[4] = {kb.x, kb.y, kb.z, kb.w};
#pragma unroll
            for (int ii = 0; ii < 4; ii++)
#pragma unroll
                for (int jj = 0; jj < 4; jj++)
                    s[ii][jj] = fmaf(qv[ii], kv[jj], s[ii][jj]);
        }

        // scale + local row max
        float mloc[4];
#pragma unroll
        for (int ii = 0; ii < 4; ii++) {
#pragma unroll
            for (int jj = 0; jj < 4; jj++) s[ii][jj] *= ATT_SCALE;
            mloc[ii] = fmaxf(fmaxf(s[ii][0], s[ii][1]), fmaxf(s[ii][2], s[ii][3]));
        }
        // reduce max over the 16 lanes sharing these rows (tx = lane & 15)
#pragma unroll
        for (int off = 8; off; off >>= 1)
#pragma unroll
            for (int ii = 0; ii < 4; ii++)
                mloc[ii] = fmaxf(mloc[ii], __shfl_xor_sync(0xffffffffu, mloc[ii], off));

        float alpha[4];
#pragma unroll
        for (int ii = 0; ii < 4; ii++) {
            float mn  = fmaxf(m_run[ii], mloc[ii]);
            alpha[ii] = __expf(m_run[ii] - mn);
            m_run[ii] = mn;
        }

        // p = exp(s - m), row sums
        float rsum[4];
#pragma unroll
        for (int ii = 0; ii < 4; ii++) {
            float acc = 0.f;
#pragma unroll
            for (int jj = 0; jj < 4; jj++) {
                float p = __expf(s[ii][jj] - m_run[ii]);
                s[ii][jj] = p;
                acc += p;
            }
            rsum[ii] = acc;
        }
#pragma unroll
        for (int off = 8; off; off >>= 1)
#pragma unroll
            for (int ii = 0; ii < 4; ii++)
                rsum[ii] += __shfl_xor_sync(0xffffffffu, rsum[ii], off);

#pragma unroll
        for (int ii = 0; ii < 4; ii++) {
            l_run[ii] = l_run[ii] * alpha[ii] + rsum[ii];
#pragma unroll
            for (int dd = 0; dd < 4; dd++) o[ii][dd] *= alpha[ii];
        }

        // stash P to smem
#pragma unroll
        for (int ii = 0; ii < 4; ii++) {
            float4 p4 = make_float4(s[ii][0], s[ii][1], s[ii][2], s[ii][3]);
            *(float4*)&ps[(ty * 4 + ii) * 68 + tx * 4] = p4;
        }
        __syncthreads();

        // O += P * V^T   (o[ii][dd]: row i = ty*4+ii, col d = tx*4+dd)
#pragma unroll 8
        for (int j = 0; j < 64; j++) {
            float4 vv4 = *(const float4*)&vts[j * 68 + tx * 4];
            float va[4] = {vv4.x, vv4.y, vv4.z, vv4.w};
#pragma unroll
            for (int ii = 0; ii < 4; ii++) {
                float pv = ps[(ty * 4 + ii) * 68 + j];
#pragma unroll
                for (int dd = 0; dd < 4; dd++)
                    o[ii][dd] = fmaf(pv, va[dd], o[ii][dd]);
            }
        }
    }

    // normalize and transpose via smem (reuse ps as [d][i] pitch 68)
    __syncthreads();
#pragma unroll
    for (int ii = 0; ii < 4; ii++) {
        float inv = 1.f / l_run[ii];
#pragma unroll
        for (int dd = 0; dd < 4; dd++)
            ps[(tx * 4 + dd) * 68 + ty * 4 + ii] = o[ii][dd] * inv;
    }
    __syncthreads();
#pragma unroll
    for (int r = 0; r < 16; r++) {
        int flat = tid + r * 256;
        int d = flat >> 6, i = flat & 63;
        out[base + (size_t)d * LSEQ + i0 + i] = ps[d * 68 + i];
    }
}

// ---------------------------------------------------------------------------
extern "C" void kernel_launch(void* const* d_in, const int* in_sizes, int n_in,
                              void* d_out, int out_size)
{
    const float* x  = (const float*)d_in[0];
    const float* w0 = (const float*)d_in[1];
    const float* b0 = (const float*)d_in[2];
    const float* w1 = (const float*)d_in[3];
    const float* b1 = (const float*)d_in[4];
    const float* w2 = (const float*)d_in[5];
    const float* b2 = (const float*)d_in[6];
    float* out = (float*)d_out;

    dim3 cgrid(32, 8, BATCH);   // l-tiles, co-tiles, batch
    conv_qkv_kernel<<<cgrid, 256>>>(x, w0, b0, 0);
    conv_qkv_kernel<<<cgrid, 256>>>(x, w1, b1, 1);
    conv_qkv_kernel<<<cgrid, 256>>>(x, w2, b2, 2);

    const int SMEM = (4096 + 4096 + 64 * 68 + 64 * 68) * 4;   // 67584 B
    cudaFuncSetAttribute(attn_kernel,
                         cudaFuncAttributeMaxDynamicSharedMemorySize, SMEM);
    dim3 agrid(32, 64);          // q-tiles, b*h
    attn_kernel<<<agrid, 256, SMEM>>>(out);
}

// round 3
// speedup vs baseline: 1.3347x; 1.3347x over previous
#include <cuda_runtime.h>

#define LSEQ 2048
#define BATCH 8
// 1/sqrt(512)
#define ATT_SCALE 0.044194173824159216f

// Scratch for q/k/v projections: [B, C, L] each = 33.5 MB
__device__ float g_q[BATCH * 512 * LSEQ];
__device__ float g_k[BATCH * 512 * LSEQ];
__device__ float g_v[BATCH * 512 * LSEQ];

// ---------------------------------------------------------------------------
// Conv1d projections (all 3 fused into one launch via blockIdx.z).
//   y[b, co, l] = bias[co] + sum_{ci,k} w[co, ci, k] * x[b, ci, l + k - 1]
// Tile: 128 co x 128 l, 256 threads, 8x8 micro-tile per thread.
// ---------------------------------------------------------------------------
__global__ void __launch_bounds__(256) conv_qkv_kernel(
    const float* __restrict__ x,
    const float* __restrict__ w0, const float* __restrict__ bb0,
    const float* __restrict__ w1, const float* __restrict__ bb1,
    const float* __restrict__ w2, const float* __restrict__ bb2)
{
    const int c = blockIdx.z % 3;
    const int b = blockIdx.z / 3;
    const float* w    = (c == 0) ? w0  : (c == 1) ? w1  : w2;
    const float* bias = (c == 0) ? bb0 : (c == 1) ? bb1 : bb2;
    float* y          = (c == 0) ? g_q : (c == 1) ? g_k : g_v;

    const int co0 = blockIdx.y * 128;
    const int l0  = blockIdx.x * 128;
    const int tid = threadIdx.x;
    const int ty  = tid >> 4;    // 0..15 -> co micro-rows
    const int tx  = tid & 15;    // 0..15 -> l micro-cols

    __shared__ float ws[24 * 128];   // [ci*3+k][co]
    __shared__ float xs[8][132];     // [ci][p], p = l-l0+1, valid 0..129

    float acc[8][8];
#pragma unroll
    for (int ii = 0; ii < 8; ii++)
#pragma unroll
        for (int jj = 0; jj < 8; jj++) acc[ii][jj] = 0.f;

    for (int ci0 = 0; ci0 < 512; ci0 += 8) {
        __syncthreads();
        // weights: 128co x 24 contiguous floats (ci chunk*3+k) = 3072
#pragma unroll
        for (int r = 0; r < 12; r++) {
            int flat = tid + r * 256;
            int co   = flat / 24;
            int cik  = flat - co * 24;
            ws[cik * 128 + co] = w[(size_t)(co0 + co) * 1536 + ci0 * 3 + cik];
        }
        // x: 8 ci x 130 (halo, zero-padded at edges)
#pragma unroll
        for (int r = 0; r < 5; r++) {
            int flat = tid + r * 256;
            if (flat < 8 * 130) {
                int ci = flat / 130;
                int p  = flat - ci * 130;
                int gl = l0 - 1 + p;
                float v = 0.f;
                if (gl >= 0 && gl < LSEQ)
                    v = x[((size_t)b * 512 + ci0 + ci) * LSEQ + gl];
                xs[ci][p] = v;
            }
        }
        __syncthreads();

#pragma unroll
        for (int ci = 0; ci < 8; ci++) {
            float xv[10];
            float4 xa = *(const float4*)&xs[ci][tx * 8];
            float4 xb = *(const float4*)&xs[ci][tx * 8 + 4];
            xv[0] = xa.x; xv[1] = xa.y; xv[2] = xa.z; xv[3] = xa.w;
            xv[4] = xb.x; xv[5] = xb.y; xv[6] = xb.z; xv[7] = xb.w;
            xv[8] = xs[ci][tx * 8 + 8];
            xv[9] = xs[ci][tx * 8 + 9];
#pragma unroll
            for (int kk = 0; kk < 3; kk++) {
                float4 wa4 = *(const float4*)&ws[(ci * 3 + kk) * 128 + ty * 8];
                float4 wb4 = *(const float4*)&ws[(ci * 3 + kk) * 128 + ty * 8 + 4];
                float wa[8] = {wa4.x, wa4.y, wa4.z, wa4.w,
                               wb4.x, wb4.y, wb4.z, wb4.w};
#pragma unroll
                for (int ii = 0; ii < 8; ii++)
#pragma unroll
                    for (int jj = 0; jj < 8; jj++)
                        acc[ii][jj] = fmaf(wa[ii], xv[jj + kk], acc[ii][jj]);
            }
        }
    }

#pragma unroll
    for (int ii = 0; ii < 8; ii++) {
        int co   = co0 + ty * 8 + ii;
        float bv = bias[co];
        float4 o0, o1;
        o0.x = acc[ii][0] + bv; o0.y = acc[ii][1] + bv;
        o0.z = acc[ii][2] + bv; o0.w = acc[ii][3] + bv;
        o1.x = acc[ii][4] + bv; o1.y = acc[ii][5] + bv;
        o1.z = acc[ii][6] + bv; o1.w = acc[ii][7] + bv;
        size_t off = ((size_t)b * 512 + co) * LSEQ + l0 + tx * 8;
        *(float4*)&y[off]     = o0;
        *(float4*)&y[off + 4] = o1;
    }
}

// ---------------------------------------------------------------------------
// Flash attention fp32. BM=128 queries x BN=64 keys, 256 threads.
// S micro-tile 8x4 (ty covers 128 i, tx covers 64 j); O micro-tile 8x4 (d).
// smem (dynamic, 101376 B):
//   qs[64 d][128 i]  ks[64 d][64 j]  vts[64 j][68 d]  ps[128 i][68 j]
// ---------------------------------------------------------------------------
__global__ void __launch_bounds__(256) attn_kernel(float* __restrict__ out)
{
    extern __shared__ float sm[];
    float* qs  = sm;                  // 8192
    float* ks  = qs + 8192;           // 4096
    float* vts = ks + 4096;           // 4352
    float* ps  = vts + 4352;          // 8704

    const int bh  = blockIdx.y;           // b*H + h
    const int i0  = blockIdx.x * 128;     // query tile origin
    const int tid = threadIdx.x;
    const int ty  = tid >> 4;
    const int tx  = tid & 15;
    const size_t base = (size_t)bh * 64 * LSEQ;

    // load Q tile qs[d][i] : 2048 float4
#pragma unroll
    for (int r = 0; r < 8; r++) {
        int f4 = tid + r * 256;
        int d = f4 >> 5, ig = f4 & 31;
        float4 v = *(const float4*)&g_q[base + (size_t)d * LSEQ + i0 + ig * 4];
        *(float4*)&qs[d * 128 + ig * 4] = v;
    }

    float m_run[8], l_run[8], o[8][4];
#pragma unroll
    for (int ii = 0; ii < 8; ii++) {
        m_run[ii] = -1e30f;
        l_run[ii] = 0.f;
#pragma unroll
        for (int dd = 0; dd < 4; dd++) o[ii][dd] = 0.f;
    }

    for (int m0 = 0; m0 < LSEQ; m0 += 64) {
        __syncthreads();   // prior PV done before overwriting ks/vts
        // load K [d][j] and V transposed [j][d]
#pragma unroll
        for (int r = 0; r < 4; r++) {
            int f4 = tid + r * 256;
            int d = f4 >> 4, jg = f4 & 15;
            float4 kv = *(const float4*)&g_k[base + (size_t)d * LSEQ + m0 + jg * 4];
            *(float4*)&ks[d * 64 + jg * 4] = kv;
            float4 vv = *(const float4*)&g_v[base + (size_t)d * LSEQ + m0 + jg * 4];
            vts[(jg * 4 + 0) * 68 + d] = vv.x;
            vts[(jg * 4 + 1) * 68 + d] = vv.y;
            vts[(jg * 4 + 2) * 68 + d] = vv.z;
            vts[(jg * 4 + 3) * 68 + d] = vv.w;
        }
        __syncthreads();

        // S = Q^T K
        float s[8][4];
#pragma unroll
        for (int ii = 0; ii < 8; ii++)
#pragma unroll
            for (int jj = 0; jj < 4; jj++) s[ii][jj] = 0.f;

#pragma unroll 16
        for (int d = 0; d < 64; d++) {
            float4 qa = *(const float4*)&qs[d * 128 + ty * 8];
            float4 qb = *(const float4*)&qs[d * 128 + ty * 8 + 4];
            float4 kb = *(const float4*)&ks[d * 64 + tx * 4];
            float qv[8] = {qa.x, qa.y, qa.z, qa.w, qb.x, qb.y, qb.z, qb.w};
            float kv[4] = {kb.x, kb.y, kb.z, kb.w};
#pragma unroll
            for (int ii = 0; ii < 8; ii++)
#pragma unroll
                for (int jj = 0; jj < 4; jj++)
                    s[ii][jj] = fmaf(qv[ii], kv[jj], s[ii][jj]);
        }

        // scale + local row max
        float mloc[8];
#pragma unroll
        for (int ii = 0; ii < 8; ii++) {
#pragma unroll
            for (int jj = 0; jj < 4; jj++) s[ii][jj] *= ATT_SCALE;
            mloc[ii] = fmaxf(fmaxf(s[ii][0], s[ii][1]), fmaxf(s[ii][2], s[ii][3]));
        }
#pragma unroll
        for (int off = 8; off; off >>= 1)
#pragma unroll
            for (int ii = 0; ii < 8; ii++)
                mloc[ii] = fmaxf(mloc[ii], __shfl_xor_sync(0xffffffffu, mloc[ii], off));

        float rsum[8];
#pragma unroll
        for (int ii = 0; ii < 8; ii++) {
            float mn    = fmaxf(m_run[ii], mloc[ii]);
            float alpha = __expf(m_run[ii] - mn);
            m_run[ii]   = mn;
            float acc = 0.f;
#pragma unroll
            for (int jj = 0; jj < 4; jj++) {
                float p = __expf(s[ii][jj] - mn);
                s[ii][jj] = p;
                acc += p;
            }
            rsum[ii] = acc;
            l_run[ii] *= alpha;
#pragma unroll
            for (int dd = 0; dd < 4; dd++) o[ii][dd] *= alpha;
        }
#pragma unroll
        for (int off = 8; off; off >>= 1)
#pragma unroll
            for (int ii = 0; ii < 8; ii++)
                rsum[ii] += __shfl_xor_sync(0xffffffffu, rsum[ii], off);
#pragma unroll
        for (int ii = 0; ii < 8; ii++) l_run[ii] += rsum[ii];

        // P -> smem
#pragma unroll
        for (int ii = 0; ii < 8; ii++) {
            float4 p4 = make_float4(s[ii][0], s[ii][1], s[ii][2], s[ii][3]);
            *(float4*)&ps[(ty * 8 + ii) * 68 + tx * 4] = p4;
        }
        __syncthreads();

        // O += P * V^T
#pragma unroll 4
        for (int j0 = 0; j0 < 64; j0 += 4) {
            float pr[8][4];
#pragma unroll
            for (int ii = 0; ii < 8; ii++) {
                float4 p4 = *(const float4*)&ps[(ty * 8 + ii) * 68 + j0];
                pr[ii][0] = p4.x; pr[ii][1] = p4.y;
                pr[ii][2] = p4.z; pr[ii][3] = p4.w;
            }
#pragma unroll
            for (int jj = 0; jj < 4; jj++) {
                float4 vv = *(const float4*)&vts[(j0 + jj) * 68 + tx * 4];
                float va[4] = {vv.x, vv.y, vv.z, vv.w};
#pragma unroll
                for (int ii = 0; ii < 8; ii++)
#pragma unroll
                    for (int dd = 0; dd < 4; dd++)
                        o[ii][dd] = fmaf(pr[ii][jj], va[dd], o[ii][dd]);
            }
        }
    }

    // normalize + transpose via smem (reuse ps as [64 d][132 i])
    __syncthreads();
#pragma unroll
    for (int ii = 0; ii < 8; ii++) {
        float inv = 1.f / l_run[ii];
#pragma unroll
        for (int dd = 0; dd < 4; dd++)
            ps[(tx * 4 + dd) * 132 + ty * 8 + ii] = o[ii][dd] * inv;
    }
    __syncthreads();
#pragma unroll
    for (int r = 0; r < 8; r++) {
        int f4 = tid + r * 256;
        int d = f4 >> 5, ig = f4 & 31;
        float4 v = *(const float4*)&ps[d * 132 + ig * 4];
        *(float4*)&out[base + (size_t)d * LSEQ + i0 + ig * 4] = v;
    }
}

// ---------------------------------------------------------------------------
extern "C" void kernel_launch(void* const* d_in, const int* in_sizes, int n_in,
                              void* d_out, int out_size)
{
    const float* x  = (const float*)d_in[0];
    const float* w0 = (const float*)d_in[1];
    const float* b0 = (const float*)d_in[2];
    const float* w1 = (const float*)d_in[3];
    const float* b1 = (const float*)d_in[4];
    const float* w2 = (const float*)d_in[5];
    const float* b2 = (const float*)d_in[6];
    float* out = (float*)d_out;

    dim3 cgrid(16, 4, 24);   // l-tiles, co-tiles, batch*conv
    conv_qkv_kernel<<<cgrid, 256>>>(x, w0, b0, w1, b1, w2, b2);

    const int SMEM = (8192 + 4096 + 4352 + 8704) * 4;   // 101376 B
    cudaFuncSetAttribute(attn_kernel,
                         cudaFuncAttributeMaxDynamicSharedMemorySize, SMEM);
    dim3 agrid(16, 64);      // q-tiles, b*h
    attn_kernel<<<agrid, 256, SMEM>>>(out);
}

// round 9
// speedup vs baseline: 2.0507x; 1.5365x over previous
#include <cuda_runtime.h>
#include <cuda_bf16.h>
#include <cstdint>

#define LSEQ 2048
#define BATCH 8
// 1/sqrt(512)
#define ATT_SCALE 0.044194173824159216f

// Scratch: q/k/v fp32 projections + split-bf16 staging of w and x.
// Staging buffers typed uint4 to guarantee 16B alignment for vector loads.
__device__ float g_q[BATCH * 512 * LSEQ];
__device__ float g_k[BATCH * 512 * LSEQ];
__device__ float g_v[BATCH * 512 * LSEQ];
__device__ uint4 g_w_hi4[3 * 512 * 1536 / 8];      // [conv][co][k][ci] bf16
__device__ uint4 g_w_lo4[3 * 512 * 1536 / 8];
__device__ uint4 g_xt_hi4[BATCH * LSEQ * 512 / 8]; // [b][l][ci] bf16
__device__ uint4 g_xt_lo4[BATCH * LSEQ * 512 / 8];
#define W_HI ((__nv_bfloat16*)g_w_hi4)
#define W_LO ((__nv_bfloat16*)g_w_lo4)
#define XT_HI ((__nv_bfloat16*)g_xt_hi4)
#define XT_LO ((__nv_bfloat16*)g_xt_lo4)

__device__ __forceinline__ void split2(float f, __nv_bfloat16& h, __nv_bfloat16& l) {
    h = __float2bfloat16_rn(f);
    l = __float2bfloat16_rn(f - __bfloat162float(h));
}

// ---------------------------------------------------------------------------
// w[co][ci][k] fp32  ->  w_hi/lo[conv][co][k][ci] bf16 (split)
// ---------------------------------------------------------------------------
__global__ void __launch_bounds__(256) split_w_kernel(
    const float* __restrict__ w0, const float* __restrict__ w1,
    const float* __restrict__ w2)
{
    const int conv = blockIdx.y;
    const float* w = (conv == 0) ? w0 : (conv == 1) ? w1 : w2;
    int idx = blockIdx.x * 256 + threadIdx.x;        // co*1536 + kk*512 + ci
    int co = idx / 1536, r = idx - co * 1536;
    int kk = r >> 9, ci = r & 511;
    float f = w[(size_t)co * 1536 + ci * 3 + kk];
    __nv_bfloat16 h, l;
    split2(f, h, l);
    size_t o = (size_t)conv * 786432 + idx;
    W_HI[o] = h;
    W_LO[o] = l;
}

// ---------------------------------------------------------------------------
// x[b][ci][l] fp32 -> xt_hi/lo[b][l][ci] bf16 (split), 32x32 smem transpose
// ---------------------------------------------------------------------------
__global__ void __launch_bounds__(256) split_x_kernel(const float* __restrict__ x)
{
    __shared__ float t[32][33];
    const int b = blockIdx.z, c0 = blockIdx.y * 32, l0 = blockIdx.x * 32;
    const int tx = threadIdx.x & 31, ty = threadIdx.x >> 5;   // 32 x 8
#pragma unroll
    for (int r = 0; r < 32; r += 8)
        t[ty + r][tx] = x[((size_t)b * 512 + c0 + ty + r) * LSEQ + l0 + tx];
    __syncthreads();
#pragma unroll
    for (int r = 0; r < 32; r += 8) {
        float v = t[tx][ty + r];
        __nv_bfloat16 h, l;
        split2(v, h, l);
        size_t o = ((size_t)b * LSEQ + l0 + ty + r) * 512 + c0 + tx;
        XT_HI[o] = h;
        XT_LO[o] = l;
    }
}

// ---------------------------------------------------------------------------
// mma.sync m16n8k16 bf16 (base PTX, legal on compute_103)
// ---------------------------------------------------------------------------
__device__ __forceinline__ void mma_bf16(float acc[4], const uint32_t a[4],
                                         const uint32_t b[2])
{
    asm volatile(
        "mma.sync.aligned.m16n8k16.row.col.f32.bf16.bf16.f32 "
        "{%0,%1,%2,%3}, {%4,%5,%6,%7}, {%8,%9}, {%0,%1,%2,%3};\n"
        : "+f"(acc[0]), "+f"(acc[1]), "+f"(acc[2]), "+f"(acc[3])
        : "r"(a[0]), "r"(a[1]), "r"(a[2]), "r"(a[3]), "r"(b[0]), "r"(b[1]));
}

// ---------------------------------------------------------------------------
// Conv1d projections via HMMA, split-bf16 3-term.
// GEMM per (b,conv): Y[512 co][2048 l] = W[co][r] * X[r][l], r = k*512+ci,
// X[r][l] = x[ci][l+k-1].  CTA tile 128co x 64l, 48 K-chunks of 32.
// Warps 2(m) x 4(n); warp tile 64co x 16l -> 4 mtiles x 2 ntiles.
// smem: A[128 co][40 bf16 pitch] hi/lo, B[64 l][40 bf16 pitch] hi/lo.
// ---------------------------------------------------------------------------
__global__ void __launch_bounds__(256) conv_qkv_mma(
    const float* __restrict__ bb0, const float* __restrict__ bb1,
    const float* __restrict__ bb2)
{
    __shared__ uint32_t ash[2560 * 2];   // hi @0, lo @2560 (words)
    __shared__ uint32_t bsh[1280 * 2];   // hi @0, lo @1280

    const int c = blockIdx.z % 3;
    const int b = blockIdx.z / 3;
    const float* bias = (c == 0) ? bb0 : (c == 1) ? bb1 : bb2;
    float* y          = (c == 0) ? g_q : (c == 1) ? g_k : g_v;
    const __nv_bfloat16* whi = W_HI + (size_t)c * 786432;
    const __nv_bfloat16* wlo = W_LO + (size_t)c * 786432;

    const int co0 = blockIdx.y * 128;
    const int l0  = blockIdx.x * 64;
    const int tid = threadIdx.x;
    const int wid = tid >> 5, lane = tid & 31;
    const int wm = wid >> 2, wn = wid & 3;
    const int g = lane >> 2, t4 = lane & 3;

    float acc[4][2][4];
#pragma unroll
    for (int mt = 0; mt < 4; mt++)
#pragma unroll
        for (int nt = 0; nt < 2; nt++)
#pragma unroll
            for (int q = 0; q < 4; q++) acc[mt][nt][q] = 0.f;

    // fill-thread mappings
    const int a_co = tid >> 1;            // 0..127
    const int b_l  = tid >> 2;            // 0..63
    const int b_sg = (tid & 3) * 8;       // 0,8,16,24 (bf16)

    for (int ch = 0; ch < 48; ch++) {
        const int kk  = ch >> 4;
        const int ci0 = (ch & 15) << 5;
        __syncthreads();
        // ---- A fill: w_hi/lo[co0+a_co][kk*512 + ci0 + 0..31]
        {
            size_t base = (size_t)(co0 + a_co) * 1536 + kk * 512 + ci0;
#pragma unroll
            for (int it = 0; it < 2; it++) {
                int seg = ((tid & 1) + 2 * it) * 8;   // 0,16 or 8,24
                uint4 vh = *(const uint4*)(whi + base + seg);
                uint4 vl = *(const uint4*)(wlo + base + seg);
                *(uint4*)&ash[a_co * 20 + seg / 2]        = vh;
                *(uint4*)&ash[2560 + a_co * 20 + seg / 2] = vl;
            }
        }
        // ---- B fill: xt_hi/lo[b][l0+b_l+kk-1][ci0 + b_sg..+7]
        {
            int gl = l0 + b_l + kk - 1;
            uint4 vh = make_uint4(0, 0, 0, 0), vl = make_uint4(0, 0, 0, 0);
            if (gl >= 0 && gl < LSEQ) {
                size_t base = ((size_t)b * LSEQ + gl) * 512 + ci0 + b_sg;
                vh = *(const uint4*)(XT_HI + base);
                vl = *(const uint4*)(XT_LO + base);
            }
            *(uint4*)&bsh[b_l * 20 + b_sg / 2]        = vh;
            *(uint4*)&bsh[1280 + b_l * 20 + b_sg / 2] = vl;
        }
        __syncthreads();

        // ---- MMA: 2 k-steps of 16
#pragma unroll
        for (int ks = 0; ks < 2; ks++) {
            uint32_t Ah[4][4], Al[4][4], Bh[2][2], Bl[2][2];
#pragma unroll
            for (int mt = 0; mt < 4; mt++) {
                int r0 = (wm * 64 + mt * 16 + g) * 20 + ks * 8 + t4;
                int r1 = r0 + 160;   // +8 rows
                Ah[mt][0] = ash[r0];     Ah[mt][1] = ash[r1];
                Ah[mt][2] = ash[r0 + 4]; Ah[mt][3] = ash[r1 + 4];
                Al[mt][0] = ash[2560 + r0];     Al[mt][1] = ash[2560 + r1];
                Al[mt][2] = ash[2560 + r0 + 4]; Al[mt][3] = ash[2560 + r1 + 4];
            }
#pragma unroll
            for (int nt = 0; nt < 2; nt++) {
                int c0w = (wn * 16 + nt * 8 + g) * 20 + ks * 8 + t4;
                Bh[nt][0] = bsh[c0w]; Bh[nt][1] = bsh[c0w + 4];
                Bl[nt][0] = bsh[1280 + c0w]; Bl[nt][1] = bsh[1280 + c0w + 4];
            }
#pragma unroll
            for (int mt = 0; mt < 4; mt++)
#pragma unroll
                for (int nt = 0; nt < 2; nt++) {
                    mma_bf16(acc[mt][nt], Ah[mt], Bh[nt]);
                    mma_bf16(acc[mt][nt], Ah[mt], Bl[nt]);
                    mma_bf16(acc[mt][nt], Al[mt], Bh[nt]);
                }
        }
    }

    // ---- epilogue: bias + store fp32
#pragma unroll
    for (int mt = 0; mt < 4; mt++) {
        int co = co0 + wm * 64 + mt * 16 + g;
        float bv0 = bias[co], bv1 = bias[co + 8];
#pragma unroll
        for (int nt = 0; nt < 2; nt++) {
            int lc = l0 + wn * 16 + nt * 8 + t4 * 2;
            size_t o0 = ((size_t)b * 512 + co) * LSEQ + lc;
            float2 v0 = make_float2(acc[mt][nt][0] + bv0, acc[mt][nt][1] + bv0);
            float2 v1 = make_float2(acc[mt][nt][2] + bv1, acc[mt][nt][3] + bv1);
            *(float2*)&y[o0]              = v0;
            *(float2*)&y[o0 + 8 * LSEQ]   = v1;
        }
    }
}

// ---------------------------------------------------------------------------
// Flash attention fp32 (unchanged, known-good). BM=128 x BN=64, 256 threads.
// ---------------------------------------------------------------------------
__global__ void __launch_bounds__(256) attn_kernel(float* __restrict__ out)
{
    extern __shared__ float smf[];
    float* qs  = smf;                 // 8192
    float* ks  = qs + 8192;           // 4096
    float* vts = ks + 4096;           // 4352
    float* ps  = vts + 4352;          // 8704

    const int bh  = blockIdx.y;
    const int i0  = blockIdx.x * 128;
    const int tid = threadIdx.x;
    const int ty  = tid >> 4;
    const int tx  = tid & 15;
    const size_t base = (size_t)bh * 64 * LSEQ;

#pragma unroll
    for (int r = 0; r < 8; r++) {
        int f4 = tid + r * 256;
        int d = f4 >> 5, ig = f4 & 31;
        float4 v = *(const float4*)&g_q[base + (size_t)d * LSEQ + i0 + ig * 4];
        *(float4*)&qs[d * 128 + ig * 4] = v;
    }

    float m_run[8], l_run[8], o[8][4];
#pragma unroll
    for (int ii = 0; ii < 8; ii++) {
        m_run[ii] = -1e30f;
        l_run[ii] = 0.f;
#pragma unroll
        for (int dd = 0; dd < 4; dd++) o[ii][dd] = 0.f;
    }

    for (int m0 = 0; m0 < LSEQ; m0 += 64) {
        __syncthreads();
#pragma unroll
        for (int r = 0; r < 4; r++) {
            int f4 = tid + r * 256;
            int d = f4 >> 4, jg = f4 & 15;
            float4 kv = *(const float4*)&g_k[base + (size_t)d * LSEQ + m0 + jg * 4];
            *(float4*)&ks[d * 64 + jg * 4] = kv;
            float4 vv = *(const float4*)&g_v[base + (size_t)d * LSEQ + m0 + jg * 4];
            vts[(jg * 4 + 0) * 68 + d] = vv.x;
            vts[(jg * 4 + 1) * 68 + d] = vv.y;
            vts[(jg * 4 + 2) * 68 + d] = vv.z;
            vts[(jg * 4 + 3) * 68 + d] = vv.w;
        }
        __syncthreads();

        float s[8][4];
#pragma unroll
        for (int ii = 0; ii < 8; ii++)
#pragma unroll
            for (int jj = 0; jj < 4; jj++) s[ii][jj] = 0.f;

#pragma unroll 16
        for (int d = 0; d < 64; d++) {
            float4 qa = *(const float4*)&qs[d * 128 + ty * 8];
            float4 qb = *(const float4*)&qs[d * 128 + ty * 8 + 4];
            float4 kb = *(const float4*)&ks[d * 64 + tx * 4];
            float qv[8] = {qa.x, qa.y, qa.z, qa.w, qb.x, qb.y, qb.z, qb.w};
            float kv[4] = {kb.x, kb.y, kb.z, kb.w};
#pragma unroll
            for (int ii = 0; ii < 8; ii++)
#pragma unroll
                for (int jj = 0; jj < 4; jj++)
                    s[ii][jj] = fmaf(qv[ii], kv[jj], s[ii][jj]);
        }

        float mloc[8];
#pragma unroll
        for (int ii = 0; ii < 8; ii++) {
#pragma unroll
            for (int jj = 0; jj < 4; jj++) s[ii][jj] *= ATT_SCALE;
            mloc[ii] = fmaxf(fmaxf(s[ii][0], s[ii][1]), fmaxf(s[ii][2], s[ii][3]));
        }
#pragma unroll
        for (int off = 8; off; off >>= 1)
#pragma unroll
            for (int ii = 0; ii < 8; ii++)
                mloc[ii] = fmaxf(mloc[ii], __shfl_xor_sync(0xffffffffu, mloc[ii], off));

        float rsum[8];
#pragma unroll
        for (int ii = 0; ii < 8; ii++) {
            float mn    = fmaxf(m_run[ii], mloc[ii]);
            float alpha = __expf(m_run[ii] - mn);
            m_run[ii]   = mn;
            float acc = 0.f;
#pragma unroll
            for (int jj = 0; jj < 4; jj++) {
                float p = __expf(s[ii][jj] - mn);
                s[ii][jj] = p;
                acc += p;
            }
            rsum[ii] = acc;
            l_run[ii] *= alpha;
#pragma unroll
            for (int dd = 0; dd < 4; dd++) o[ii][dd] *= alpha;
        }
#pragma unroll
        for (int off = 8; off; off >>= 1)
#pragma unroll
            for (int ii = 0; ii < 8; ii++)
                rsum[ii] += __shfl_xor_sync(0xffffffffu, rsum[ii], off);
#pragma unroll
        for (int ii = 0; ii < 8; ii++) l_run[ii] += rsum[ii];

#pragma unroll
        for (int ii = 0; ii < 8; ii++) {
            float4 p4 = make_float4(s[ii][0], s[ii][1], s[ii][2], s[ii][3]);
            *(float4*)&ps[(ty * 8 + ii) * 68 + tx * 4] = p4;
        }
        __syncthreads();

#pragma unroll 4
        for (int j0 = 0; j0 < 64; j0 += 4) {
            float pr[8][4];
#pragma unroll
            for (int ii = 0; ii < 8; ii++) {
                float4 p4 = *(const float4*)&ps[(ty * 8 + ii) * 68 + j0];
                pr[ii][0] = p4.x; pr[ii][1] = p4.y;
                pr[ii][2] = p4.z; pr[ii][3] = p4.w;
            }
#pragma unroll
            for (int jj = 0; jj < 4; jj++) {
                float4 vv = *(const float4*)&vts[(j0 + jj) * 68 + tx * 4];
                float va[4] = {vv.x, vv.y, vv.z, vv.w};
#pragma unroll
                for (int ii = 0; ii < 8; ii++)
#pragma unroll
                    for (int dd = 0; dd < 4; dd++)
                        o[ii][dd] = fmaf(pr[ii][jj], va[dd], o[ii][dd]);
            }
        }
    }

    __syncthreads();
#pragma unroll
    for (int ii = 0; ii < 8; ii++) {
        float inv = 1.f / l_run[ii];
#pragma unroll
        for (int dd = 0; dd < 4; dd++)
            ps[(tx * 4 + dd) * 132 + ty * 8 + ii] = o[ii][dd] * inv;
    }
    __syncthreads();
#pragma unroll
    for (int r = 0; r < 8; r++) {
        int f4 = tid + r * 256;
        int d = f4 >> 5, ig = f4 & 31;
        float4 v = *(const float4*)&ps[d * 132 + ig * 4];
        *(float4*)&out[base + (size_t)d * LSEQ + i0 + ig * 4] = v;
    }
}

// ---------------------------------------------------------------------------
extern "C" void kernel_launch(void* const* d_in, const int* in_sizes, int n_in,
                              void* d_out, int out_size)
{
    const float* x  = (const float*)d_in[0];
    const float* w0 = (const float*)d_in[1];
    const float* b0 = (const float*)d_in[2];
    const float* w1 = (const float*)d_in[3];
    const float* b1 = (const float*)d_in[4];
    const float* w2 = (const float*)d_in[5];
    const float* b2 = (const float*)d_in[6];
    float* out = (float*)d_out;

    // 1) split-precision staging
    dim3 wgrid(786432 / 256, 3);
    split_w_kernel<<<wgrid, 256>>>(w0, w1, w2);
    dim3 xgrid(LSEQ / 32, 16, BATCH);
    split_x_kernel<<<xgrid, 256>>>(x);

    // 2) conv projections on tensor cores
    dim3 cgrid(LSEQ / 64, 4, 24);   // l-tiles, co-tiles, batch*conv
    conv_qkv_mma<<<cgrid, 256>>>(b0, b1, b2);

    // 3) attention
    const int SMEM = (8192 + 4096 + 4352 + 8704) * 4;   // 101376 B
    cudaFuncSetAttribute(attn_kernel,
                         cudaFuncAttributeMaxDynamicSharedMemorySize, SMEM);
    dim3 agrid(16, 64);      // q-tiles, b*h
    attn_kernel<<<agrid, 256, SMEM>>>(out);
}

// round 10
// speedup vs baseline: 2.9878x; 1.4570x over previous
#include <cuda_runtime.h>
#include <cuda_bf16.h>
#include <cstdint>

#define LSEQ 2048
#define BATCH 8
// 1/sqrt(512)
#define ATT_SCALE 0.044194173824159216f

// Scratch: q/k/v fp32 projections + split-bf16 staging of w and x.
__device__ float g_q[BATCH * 512 * LSEQ];
__device__ float g_k[BATCH * 512 * LSEQ];
__device__ float g_v[BATCH * 512 * LSEQ];
__device__ uint4 g_w_hi4[3 * 512 * 1536 / 8];      // [conv][co][k][ci] bf16
__device__ uint4 g_w_lo4[3 * 512 * 1536 / 8];
__device__ uint4 g_xt_hi4[BATCH * LSEQ * 512 / 8]; // [b][l][ci] bf16
__device__ uint4 g_xt_lo4[BATCH * LSEQ * 512 / 8];
#define W_HI ((__nv_bfloat16*)g_w_hi4)
#define W_LO ((__nv_bfloat16*)g_w_lo4)
#define XT_HI ((__nv_bfloat16*)g_xt_hi4)
#define XT_LO ((__nv_bfloat16*)g_xt_lo4)

__device__ __forceinline__ void split2(float f, __nv_bfloat16& h, __nv_bfloat16& l) {
    h = __float2bfloat16_rn(f);
    l = __float2bfloat16_rn(f - __bfloat162float(h));
}

// pack two floats as bf16x2: f0 -> low half, f1 -> high half
__device__ __forceinline__ uint32_t cvt_bf16x2(float f1, float f0) {
    uint32_t r;
    asm("cvt.rn.bf16x2.f32 %0, %1, %2;" : "=r"(r) : "f"(f1), "f"(f0));
    return r;
}
// split-precision pack: h = bf16x2(f0,f1), l = bf16x2 of residuals
__device__ __forceinline__ void split_pack(float f1, float f0,
                                           uint32_t& h, uint32_t& l) {
    h = cvt_bf16x2(f1, f0);
    float h0 = __uint_as_float(h << 16);
    float h1 = __uint_as_float(h & 0xffff0000u);
    l = cvt_bf16x2(f1 - h1, f0 - h0);
}

// ---------------------------------------------------------------------------
// w[co][ci][k] fp32  ->  w_hi/lo[conv][co][k][ci] bf16 (split)
// ---------------------------------------------------------------------------
__global__ void __launch_bounds__(256) split_w_kernel(
    const float* __restrict__ w0, const float* __restrict__ w1,
    const float* __restrict__ w2)
{
    const int conv = blockIdx.y;
    const float* w = (conv == 0) ? w0 : (conv == 1) ? w1 : w2;
    int idx = blockIdx.x * 256 + threadIdx.x;        // co*1536 + kk*512 + ci
    int co = idx / 1536, r = idx - co * 1536;
    int kk = r >> 9, ci = r & 511;
    float f = w[(size_t)co * 1536 + ci * 3 + kk];
    __nv_bfloat16 h, l;
    split2(f, h, l);
    size_t o = (size_t)conv * 786432 + idx;
    W_HI[o] = h;
    W_LO[o] = l;
}

// ---------------------------------------------------------------------------
// x[b][ci][l] fp32 -> xt_hi/lo[b][l][ci] bf16 (split), 32x32 smem transpose
// ---------------------------------------------------------------------------
__global__ void __launch_bounds__(256) split_x_kernel(const float* __restrict__ x)
{
    __shared__ float t[32][33];
    const int b = blockIdx.z, c0 = blockIdx.y * 32, l0 = blockIdx.x * 32;
    const int tx = threadIdx.x & 31, ty = threadIdx.x >> 5;   // 32 x 8
#pragma unroll
    for (int r = 0; r < 32; r += 8)
        t[ty + r][tx] = x[((size_t)b * 512 + c0 + ty + r) * LSEQ + l0 + tx];
    __syncthreads();
#pragma unroll
    for (int r = 0; r < 32; r += 8) {
        float v = t[tx][ty + r];
        __nv_bfloat16 h, l;
        split2(v, h, l);
        size_t o = ((size_t)b * LSEQ + l0 + ty + r) * 512 + c0 + tx;
        XT_HI[o] = h;
        XT_LO[o] = l;
    }
}

// ---------------------------------------------------------------------------
// mma.sync m16n8k16 bf16 (base PTX, legal on compute_103)
// ---------------------------------------------------------------------------
__device__ __forceinline__ void mma_bf16(float acc[4], const uint32_t a[4],
                                         const uint32_t b[2])
{
    asm volatile(
        "mma.sync.aligned.m16n8k16.row.col.f32.bf16.bf16.f32 "
        "{%0,%1,%2,%3}, {%4,%5,%6,%7}, {%8,%9}, {%0,%1,%2,%3};\n"
        : "+f"(acc[0]), "+f"(acc[1]), "+f"(acc[2]), "+f"(acc[3])
        : "r"(a[0]), "r"(a[1]), "r"(a[2]), "r"(a[3]), "r"(b[0]), "r"(b[1]));
}

// ---------------------------------------------------------------------------
// Conv1d projections via HMMA, split-bf16 3-term (unchanged, proven R9).
// ---------------------------------------------------------------------------
__global__ void __launch_bounds__(256) conv_qkv_mma(
    const float* __restrict__ bb0, const float* __restrict__ bb1,
    const float* __restrict__ bb2)
{
    __shared__ uint32_t ash[2560 * 2];   // hi @0, lo @2560 (words)
    __shared__ uint32_t bsh[1280 * 2];   // hi @0, lo @1280

    const int c = blockIdx.z % 3;
    const int b = blockIdx.z / 3;
    const float* bias = (c == 0) ? bb0 : (c == 1) ? bb1 : bb2;
    float* y          = (c == 0) ? g_q : (c == 1) ? g_k : g_v;
    const __nv_bfloat16* whi = W_HI + (size_t)c * 786432;
    const __nv_bfloat16* wlo = W_LO + (size_t)c * 786432;

    const int co0 = blockIdx.y * 128;
    const int l0  = blockIdx.x * 64;
    const int tid = threadIdx.x;
    const int wid = tid >> 5, lane = tid & 31;
    const int wm = wid >> 2, wn = wid & 3;
    const int g = lane >> 2, t4 = lane & 3;

    float acc[4][2][4];
#pragma unroll
    for (int mt = 0; mt < 4; mt++)
#pragma unroll
        for (int nt = 0; nt < 2; nt++)
#pragma unroll
            for (int q = 0; q < 4; q++) acc[mt][nt][q] = 0.f;

    const int a_co = tid >> 1;
    const int b_l  = tid >> 2;
    const int b_sg = (tid & 3) * 8;

    for (int ch = 0; ch < 48; ch++) {
        const int kk  = ch >> 4;
        const int ci0 = (ch & 15) << 5;
        __syncthreads();
        {
            size_t base = (size_t)(co0 + a_co) * 1536 + kk * 512 + ci0;
#pragma unroll
            for (int it = 0; it < 2; it++) {
                int seg = ((tid & 1) + 2 * it) * 8;
                uint4 vh = *(const uint4*)(whi + base + seg);
                uint4 vl = *(const uint4*)(wlo + base + seg);
                *(uint4*)&ash[a_co * 20 + seg / 2]        = vh;
                *(uint4*)&ash[2560 + a_co * 20 + seg / 2] = vl;
            }
        }
        {
            int gl = l0 + b_l + kk - 1;
            uint4 vh = make_uint4(0, 0, 0, 0), vl = make_uint4(0, 0, 0, 0);
            if (gl >= 0 && gl < LSEQ) {
                size_t base = ((size_t)b * LSEQ + gl) * 512 + ci0 + b_sg;
                vh = *(const uint4*)(XT_HI + base);
                vl = *(const uint4*)(XT_LO + base);
            }
            *(uint4*)&bsh[b_l * 20 + b_sg / 2]        = vh;
            *(uint4*)&bsh[1280 + b_l * 20 + b_sg / 2] = vl;
        }
        __syncthreads();

#pragma unroll
        for (int ks = 0; ks < 2; ks++) {
            uint32_t Ah[4][4], Al[4][4], Bh[2][2], Bl[2][2];
#pragma unroll
            for (int mt = 0; mt < 4; mt++) {
                int r0 = (wm * 64 + mt * 16 + g) * 20 + ks * 8 + t4;
                int r1 = r0 + 160;
                Ah[mt][0] = ash[r0];     Ah[mt][1] = ash[r1];
                Ah[mt][2] = ash[r0 + 4]; Ah[mt][3] = ash[r1 + 4];
                Al[mt][0] = ash[2560 + r0];     Al[mt][1] = ash[2560 + r1];
                Al[mt][2] = ash[2560 + r0 + 4]; Al[mt][3] = ash[2560 + r1 + 4];
            }
#pragma unroll
            for (int nt = 0; nt < 2; nt++) {
                int c0w = (wn * 16 + nt * 8 + g) * 20 + ks * 8 + t4;
                Bh[nt][0] = bsh[c0w]; Bh[nt][1] = bsh[c0w + 4];
                Bl[nt][0] = bsh[1280 + c0w]; Bl[nt][1] = bsh[1280 + c0w + 4];
            }
#pragma unroll
            for (int mt = 0; mt < 4; mt++)
#pragma unroll
                for (int nt = 0; nt < 2; nt++) {
                    mma_bf16(acc[mt][nt], Ah[mt], Bh[nt]);
                    mma_bf16(acc[mt][nt], Ah[mt], Bl[nt]);
                    mma_bf16(acc[mt][nt], Al[mt], Bh[nt]);
                }
        }
    }

#pragma unroll
    for (int mt = 0; mt < 4; mt++) {
        int co = co0 + wm * 64 + mt * 16 + g;
        float bv0 = bias[co], bv1 = bias[co + 8];
#pragma unroll
        for (int nt = 0; nt < 2; nt++) {
            int lc = l0 + wn * 16 + nt * 8 + t4 * 2;
            size_t o0 = ((size_t)b * 512 + co) * LSEQ + lc;
            float2 v0 = make_float2(acc[mt][nt][0] + bv0, acc[mt][nt][1] + bv0);
            float2 v1 = make_float2(acc[mt][nt][2] + bv1, acc[mt][nt][3] + bv1);
            *(float2*)&y[o0]              = v0;
            *(float2*)&y[o0 + 8 * LSEQ]   = v1;
        }
    }
}

// ---------------------------------------------------------------------------
// Flash attention on tensor cores, split-bf16 3-term for QK^T and PV.
// CTA: 128 queries (i) x full 2048 keys, BN=64 per iter, 256 threads.
// Warp w owns i rows [16w, 16w+16); per-warp S tile m16 x n64.
// smem (73728 B):
//   qs hi/lo [128 i][72 bf16 pitch], ks hi/lo [64 j][72], vs hi/lo [64 d][72]
//   epilogue staging osf [64 d][132 f32] aliases ks/vs region.
// P kept in registers: S-accumulator fragments map directly onto A-fragments.
// ---------------------------------------------------------------------------
#define PW 36   // row pitch in 32-bit words (72 bf16)

__global__ void __launch_bounds__(256, 2) attn_tc(float* __restrict__ out)
{
    extern __shared__ char smc[];
    uint32_t* qsh = (uint32_t*)(smc);
    uint32_t* qsl = (uint32_t*)(smc + 18432);
    uint32_t* ksh = (uint32_t*)(smc + 36864);
    uint32_t* ksl = (uint32_t*)(smc + 46080);
    uint32_t* vsh = (uint32_t*)(smc + 55296);
    uint32_t* vsl = (uint32_t*)(smc + 64512);
    uint16_t* qsh16 = (uint16_t*)qsh;
    uint16_t* qsl16 = (uint16_t*)qsl;
    uint16_t* ksh16 = (uint16_t*)ksh;
    uint16_t* ksl16 = (uint16_t*)ksl;
    float*    osf   = (float*)(smc + 36864);   // [64 d][132 i]

    const int bh  = blockIdx.y;
    const int i0  = blockIdx.x * 128;
    const int tid = threadIdx.x;
    const int w   = tid >> 5;
    const int lane = tid & 31;
    const int g   = lane >> 2, t4 = lane & 3;
    const size_t base = (size_t)bh * 64 * LSEQ;

    const int sd = tid >> 2;        // 0..63 (d row for staging loads)
    const int sq = tid & 3;

    // ---- Q staging: fp32 [d][i] -> split bf16 qs[i][d]
#pragma unroll
    for (int r = 0; r < 8; r++) {
        int i4 = sq * 8 + r;
        float4 v = *(const float4*)&g_q[base + (size_t)sd * LSEQ + i0 + i4 * 4];
        uint32_t h01, l01, h23, l23;
        split_pack(v.y, v.x, h01, l01);
        split_pack(v.w, v.z, h23, l23);
        int i = i4 * 4;
        qsh16[(i + 0) * 72 + sd] = (uint16_t)(h01 & 0xffff);
        qsh16[(i + 1) * 72 + sd] = (uint16_t)(h01 >> 16);
        qsh16[(i + 2) * 72 + sd] = (uint16_t)(h23 & 0xffff);
        qsh16[(i + 3) * 72 + sd] = (uint16_t)(h23 >> 16);
        qsl16[(i + 0) * 72 + sd] = (uint16_t)(l01 & 0xffff);
        qsl16[(i + 1) * 72 + sd] = (uint16_t)(l01 >> 16);
        qsl16[(i + 2) * 72 + sd] = (uint16_t)(l23 & 0xffff);
        qsl16[(i + 3) * 72 + sd] = (uint16_t)(l23 >> 16);
    }

    float oacc[8][4];
#pragma unroll
    for (int nt = 0; nt < 8; nt++)
#pragma unroll
        for (int q = 0; q < 4; q++) oacc[nt][q] = 0.f;
    float m0r = -1e30f, m1r = -1e30f, l0r = 0.f, l1r = 0.f;

    for (int m0 = 0; m0 < LSEQ; m0 += 64) {
        __syncthreads();   // prev PV done before overwriting ks/vs
        // ---- K staging: [d][j] -> ks[j][d] split
#pragma unroll
        for (int r = 0; r < 4; r++) {
            int j4 = sq * 4 + r;
            float4 v = *(const float4*)&g_k[base + (size_t)sd * LSEQ + m0 + j4 * 4];
            uint32_t h01, l01, h23, l23;
            split_pack(v.y, v.x, h01, l01);
            split_pack(v.w, v.z, h23, l23);
            int j = j4 * 4;
            ksh16[(j + 0) * 72 + sd] = (uint16_t)(h01 & 0xffff);
            ksh16[(j + 1) * 72 + sd] = (uint16_t)(h01 >> 16);
            ksh16[(j + 2) * 72 + sd] = (uint16_t)(h23 & 0xffff);
            ksh16[(j + 3) * 72 + sd] = (uint16_t)(h23 >> 16);
            ksl16[(j + 0) * 72 + sd] = (uint16_t)(l01 & 0xffff);
            ksl16[(j + 1) * 72 + sd] = (uint16_t)(l01 >> 16);
            ksl16[(j + 2) * 72 + sd] = (uint16_t)(l23 & 0xffff);
            ksl16[(j + 3) * 72 + sd] = (uint16_t)(l23 >> 16);
            // ---- V staging: natural [d][j], packed pairs
            float4 vv = *(const float4*)&g_v[base + (size_t)sd * LSEQ + m0 + j4 * 4];
            uint32_t vh01, vl01, vh23, vl23;
            split_pack(vv.y, vv.x, vh01, vl01);
            split_pack(vv.w, vv.z, vh23, vl23);
            vsh[sd * PW + j4 * 2]     = vh01;
            vsh[sd * PW + j4 * 2 + 1] = vh23;
            vsl[sd * PW + j4 * 2]     = vl01;
            vsl[sd * PW + j4 * 2 + 1] = vl23;
        }
        __syncthreads();

        // ---- S = Q^T K (3-term split)
        float sa[8][4];
#pragma unroll
        for (int nt = 0; nt < 8; nt++)
#pragma unroll
            for (int q = 0; q < 4; q++) sa[nt][q] = 0.f;

#pragma unroll
        for (int ks = 0; ks < 4; ks++) {
            uint32_t ah[4], al[4];
            int ra = (w * 16 + g) * PW + ks * 8 + t4;
            ah[0] = qsh[ra]; ah[1] = qsh[ra + 8 * PW];
            ah[2] = qsh[ra + 4]; ah[3] = qsh[ra + 8 * PW + 4];
            al[0] = qsl[ra]; al[1] = qsl[ra + 8 * PW];
            al[2] = qsl[ra + 4]; al[3] = qsl[ra + 8 * PW + 4];
#pragma unroll
            for (int jt = 0; jt < 8; jt++) {
                uint32_t bhh[2], bll[2];
                int rb = (jt * 8 + g) * PW + ks * 8 + t4;
                bhh[0] = ksh[rb]; bhh[1] = ksh[rb + 4];
                bll[0] = ksl[rb]; bll[1] = ksl[rb + 4];
                mma_bf16(sa[jt], ah, bhh);
                mma_bf16(sa[jt], ah, bll);
                mma_bf16(sa[jt], al, bhh);
            }
        }

        // ---- softmax (rows g and g+8 of this warp's 16)
        float mn0 = -1e30f, mn1 = -1e30f;
#pragma unroll
        for (int nt = 0; nt < 8; nt++) {
#pragma unroll
            for (int q = 0; q < 4; q++) sa[nt][q] *= ATT_SCALE;
            mn0 = fmaxf(mn0, fmaxf(sa[nt][0], sa[nt][1]));
            mn1 = fmaxf(mn1, fmaxf(sa[nt][2], sa[nt][3]));
        }
        mn0 = fmaxf(mn0, __shfl_xor_sync(0xffffffffu, mn0, 1));
        mn0 = fmaxf(mn0, __shfl_xor_sync(0xffffffffu, mn0, 2));
        mn1 = fmaxf(mn1, __shfl_xor_sync(0xffffffffu, mn1, 1));
        mn1 = fmaxf(mn1, __shfl_xor_sync(0xffffffffu, mn1, 2));

        float mnew0 = fmaxf(m0r, mn0), mnew1 = fmaxf(m1r, mn1);
        float alpha0 = __expf(m0r - mnew0), alpha1 = __expf(m1r - mnew1);
        m0r = mnew0; m1r = mnew1;

        float rs0 = 0.f, rs1 = 0.f;
#pragma unroll
        for (int nt = 0; nt < 8; nt++) {
            sa[nt][0] = __expf(sa[nt][0] - mnew0);
            sa[nt][1] = __expf(sa[nt][1] - mnew0);
            sa[nt][2] = __expf(sa[nt][2] - mnew1);
            sa[nt][3] = __expf(sa[nt][3] - mnew1);
            rs0 += sa[nt][0] + sa[nt][1];
            rs1 += sa[nt][2] + sa[nt][3];
        }
        rs0 += __shfl_xor_sync(0xffffffffu, rs0, 1);
        rs0 += __shfl_xor_sync(0xffffffffu, rs0, 2);
        rs1 += __shfl_xor_sync(0xffffffffu, rs1, 1);
        rs1 += __shfl_xor_sync(0xffffffffu, rs1, 2);
        l0r = l0r * alpha0 + rs0;
        l1r = l1r * alpha1 + rs1;

#pragma unroll
        for (int nt = 0; nt < 8; nt++) {
            oacc[nt][0] *= alpha0; oacc[nt][1] *= alpha0;
            oacc[nt][2] *= alpha1; oacc[nt][3] *= alpha1;
        }

        // ---- O += P V  (P from registers: acc->A-fragment identity)
#pragma unroll
        for (int ks = 0; ks < 4; ks++) {
            uint32_t ph[4], pl[4];
            split_pack(sa[2 * ks][1],     sa[2 * ks][0],     ph[0], pl[0]);
            split_pack(sa[2 * ks][3],     sa[2 * ks][2],     ph[1], pl[1]);
            split_pack(sa[2 * ks + 1][1], sa[2 * ks + 1][0], ph[2], pl[2]);
            split_pack(sa[2 * ks + 1][3], sa[2 * ks + 1][2], ph[3], pl[3]);
#pragma unroll
            for (int nt = 0; nt < 8; nt++) {
                uint32_t bhh[2], bll[2];
                int rb = (nt * 8 + g) * PW + ks * 8 + t4;
                bhh[0] = vsh[rb]; bhh[1] = vsh[rb + 4];
                bll[0] = vsl[rb]; bll[1] = vsl[rb + 4];
                mma_bf16(oacc[nt], ph, bhh);
                mma_bf16(oacc[nt], ph, bll);
                mma_bf16(oacc[nt], pl, bhh);
            }
        }
    }

    // ---- epilogue: normalize, transpose via smem, coalesced store
    __syncthreads();   // done reading vs before osf overwrites it
    {
        float inv0 = 1.f / l0r, inv1 = 1.f / l1r;
        int ir0 = w * 16 + g, ir1 = ir0 + 8;
#pragma unroll
        for (int nt = 0; nt < 8; nt++) {
            int d = nt * 8 + 2 * t4;
            osf[d * 132 + ir0]       = oacc[nt][0] * inv0;
            osf[(d + 1) * 132 + ir0] = oacc[nt][1] * inv0;
            osf[d * 132 + ir1]       = oacc[nt][2] * inv1;
            osf[(d + 1) * 132 + ir1] = oacc[nt][3] * inv1;
        }
    }
    __syncthreads();
#pragma unroll
    for (int r = 0; r < 8; r++) {
        int f4 = tid + r * 256;
        int d = f4 >> 5, ig = f4 & 31;
        float4 v = *(const float4*)&osf[d * 132 + ig * 4];
        *(float4*)&out[base + (size_t)d * LSEQ + i0 + ig * 4] = v;
    }
}

// ---------------------------------------------------------------------------
extern "C" void kernel_launch(void* const* d_in, const int* in_sizes, int n_in,
                              void* d_out, int out_size)
{
    const float* x  = (const float*)d_in[0];
    const float* w0 = (const float*)d_in[1];
    const float* b0 = (const float*)d_in[2];
    const float* w1 = (const float*)d_in[3];
    const float* b1 = (const float*)d_in[4];
    const float* w2 = (const float*)d_in[5];
    const float* b2 = (const float*)d_in[6];
    float* out = (float*)d_out;

    // 1) split-precision staging
    dim3 wgrid(786432 / 256, 3);
    split_w_kernel<<<wgrid, 256>>>(w0, w1, w2);
    dim3 xgrid(LSEQ / 32, 16, BATCH);
    split_x_kernel<<<xgrid, 256>>>(x);

    // 2) conv projections on tensor cores
    dim3 cgrid(LSEQ / 64, 4, 24);
    conv_qkv_mma<<<cgrid, 256>>>(b0, b1, b2);

    // 3) attention on tensor cores
    const int ASMEM = 73728;
    cudaFuncSetAttribute(attn_tc,
                         cudaFuncAttributeMaxDynamicSharedMemorySize, ASMEM);
    dim3 agrid(16, 64);      // q-tiles, b*h
    attn_tc<<<agrid, 256, ASMEM>>>(out);
}